// round 13
// baseline (speedup 1.0000x reference)
#include <cuda_runtime.h>

// Sinkhorn as diagonal scaling: out = (s+eps)*u9[r]*v8[c] on valid block.
// v_{2k} = 1/(M^T u_{2k-1}), u_{2k+1} = 1/(M v_{2k}), u0 = 1 on valid rows.
//
// R12: revert to R2 champion (multi-launch, 2 groups of 32 batches for L2
// residency) and fuse finalize_v into the pass kernels: each pass computes
// v = 1/acc_prev inline (4KB L2 read per CTA) and accumulates into its own
// distinct buffer g_acc[pass]. Launches 23 -> 13; groups reuse buffers on
// disjoint batch ranges so ONE upfront zero kernel suffices.

#define NB   64
#define NN   1024
#define EPS  1e-4f
#define GRP  32      // batches per group (L2 residency)
#define RPC  32      // rows per CTA

// Per-pass column-sum accumulators (allocation-free rule: __device__ globals).
// Buffer k is written by pass k and read (as v) by pass k+1 / final.
__device__ float g_acc[5][NB * NN];

__global__ void zero_acc_kernel() {
    int i = blockIdx.x * blockDim.x + threadIdx.x;
    if (i < 5 * NB * NN) ((float*)g_acc)[i] = 0.0f;
}

// Build v for this CTA's batch from a finished accumulator buffer.
// v_c = (c < nc) ? 1/acc_c : 0, held in registers (chunk f, lane-local cols).
__device__ __forceinline__ void build_v(float4 (&v4)[8],
                                        const float* __restrict__ accprev,
                                        int b, int nc, int mylim, int lane)
{
    const float4* ap = (const float4*)(accprev + b * NN);
#pragma unroll
    for (int f = 0; f < 8; f++) {
        if (128 * f < mylim) {
            float4 a = ap[f * 32 + lane];
            const int c0 = 128 * f + 4 * lane;
            v4[f].x = (c0 + 0 < nc) ? (1.0f / a.x) : 0.0f;
            v4[f].y = (c0 + 1 < nc) ? (1.0f / a.y) : 0.0f;
            v4[f].z = (c0 + 2 < nc) ? (1.0f / a.z) : 0.0f;
            v4[f].w = (c0 + 3 < nc) ? (1.0f / a.w) : 0.0f;
        } else {
            v4[f] = make_float4(0.f, 0.f, 0.f, 0.f);
        }
    }
}

// One streaming pass. FIRST=1: u=1 (computes c0 into accnext).
// FIRST=0: v = 1/accprev; per valid row: u = 1/dot(row+eps, v);
//          accnext[c] += (row[c]+eps)*u.
template <int FIRST>
__global__ __launch_bounds__(256, 2) void pass_kernel(
    const float* __restrict__ s,
    const int*   __restrict__ nrows,
    const int*   __restrict__ ncols,
    const float* __restrict__ accprev,
    float*       __restrict__ accnext,
    int batch0)
{
    const int b  = batch0 + blockIdx.y;
    const int nr = nrows[b];
    const int r0cta = blockIdx.x * RPC;
    if (r0cta >= nr) return;   // whole CTA invalid (uniform exit, no syncs yet)

    const int nc   = ncols[b];
    const int warp = threadIdx.x >> 5;
    const int lane = threadIdx.x & 31;
    const int mylim = nc - 4 * lane;   // chunk f needed iff 128*f < mylim

    const float4* sb = (const float4*)(s + (size_t)b * NN * NN);

    float4 v4[8];
    if (FIRST) {
#pragma unroll
        for (int f = 0; f < 8; f++) v4[f] = make_float4(0.f, 0.f, 0.f, 0.f);
    } else {
        build_v(v4, accprev, b, nc, mylim, lane);
    }

    float4 acc[8];
#pragma unroll
    for (int f = 0; f < 8; f++) acc[f] = make_float4(0.f, 0.f, 0.f, 0.f);

    const int rbase = r0cta + warp * 4;
    for (int i = 0; i < 4; i++) {
        int r = rbase + i;
        if (r >= nr) break;          // warp-uniform
        const float4* rp = sb + (size_t)r * 256;

        float4 x[8];
#pragma unroll
        for (int f = 0; f < 8; f++)
            if (128 * f < mylim) x[f] = rp[f * 32 + lane];
#pragma unroll
        for (int f = 0; f < 8; f++)
            if (128 * f < mylim) { x[f].x += EPS; x[f].y += EPS; x[f].z += EPS; x[f].w += EPS; }

        float u;
        if (FIRST) {
            u = 1.0f;
        } else {
            float d = 0.0f;
#pragma unroll
            for (int f = 0; f < 8; f++)
                if (128 * f < mylim)
                    d += x[f].x * v4[f].x + x[f].y * v4[f].y
                       + x[f].z * v4[f].z + x[f].w * v4[f].w;
#pragma unroll
            for (int o = 16; o; o >>= 1) d += __shfl_xor_sync(0xffffffffu, d, o);
            u = 1.0f / d;
        }
#pragma unroll
        for (int f = 0; f < 8; f++)
            if (128 * f < mylim) {
                acc[f].x += x[f].x * u; acc[f].y += x[f].y * u;
                acc[f].z += x[f].z * u; acc[f].w += x[f].w * u;
            }
    }

    // CTA-level reduction of per-warp column accumulators, then REDG per col.
    __shared__ float4 st[8][256];
#pragma unroll
    for (int f = 0; f < 8; f++) st[warp][f * 32 + lane] = acc[f];
    __syncthreads();

    const int j = threadIdx.x;           // owns columns 4j..4j+3
    float4 t = st[0][j];
#pragma unroll
    for (int w = 1; w < 8; w++) {
        float4 a = st[w][j];
        t.x += a.x; t.y += a.y; t.z += a.z; t.w += a.w;
    }
    float* ga = accnext + b * NN + 4 * j;
    atomicAdd(ga + 0, t.x);
    atomicAdd(ga + 1, t.y);
    atomicAdd(ga + 2, t.z);
    atomicAdd(ga + 3, t.w);
}

// Final pass: v8 = 1/acc4; u9 = 1/(M v8); out = (s+eps)*u9*v8 (0 outside).
__global__ __launch_bounds__(256, 2) void final_kernel(
    const float* __restrict__ s,
    float*       __restrict__ out,
    const int*   __restrict__ nrows,
    const int*   __restrict__ ncols,
    const float* __restrict__ accprev,
    int batch0)
{
    const int b  = batch0 + blockIdx.y;
    const int nr = nrows[b];
    const int nc = ncols[b];
    const int warp = threadIdx.x >> 5;
    const int lane = threadIdx.x & 31;
    const int mylim = nc - 4 * lane;

    const float4* sb = (const float4*)(s + (size_t)b * NN * NN);
    float4*       ob = (float4*)(out + (size_t)b * NN * NN);

    float4 v4[8];
    build_v(v4, accprev, b, nc, mylim, lane);

    const int rbase = blockIdx.x * RPC + warp * 4;
    const float4 z4 = make_float4(0.f, 0.f, 0.f, 0.f);

    for (int i = 0; i < 4; i++) {
        int r = rbase + i;
        float4* op = ob + (size_t)r * 256;
        if (r >= nr) {                     // invalid row: all zeros (no read)
#pragma unroll
            for (int f = 0; f < 8; f++) __stcs(&op[f * 32 + lane], z4);
            continue;
        }
        const float4* rp = sb + (size_t)r * 256;
        float4 x[8];
#pragma unroll
        for (int f = 0; f < 8; f++)
            if (128 * f < mylim) x[f] = rp[f * 32 + lane];
#pragma unroll
        for (int f = 0; f < 8; f++)
            if (128 * f < mylim) { x[f].x += EPS; x[f].y += EPS; x[f].z += EPS; x[f].w += EPS; }

        float d = 0.0f;
#pragma unroll
        for (int f = 0; f < 8; f++)
            if (128 * f < mylim)
                d += x[f].x * v4[f].x + x[f].y * v4[f].y
                   + x[f].z * v4[f].z + x[f].w * v4[f].w;
#pragma unroll
        for (int o = 16; o; o >>= 1) d += __shfl_xor_sync(0xffffffffu, d, o);
        const float u = 1.0f / d;

#pragma unroll
        for (int f = 0; f < 8; f++) {
            if (128 * f < mylim) {
                float4 o;
                o.x = x[f].x * u * v4[f].x;
                o.y = x[f].y * u * v4[f].y;
                o.z = x[f].z * u * v4[f].z;
                o.w = x[f].w * u * v4[f].w;
                __stcs(&op[f * 32 + lane], o);   // v==0 beyond ncols -> exact 0
            } else {
                __stcs(&op[f * 32 + lane], z4);
            }
        }
    }
}

extern "C" void kernel_launch(void* const* d_in, const int* in_sizes, int n_in,
                              void* d_out, int out_size)
{
    const float* s = (const float*)d_in[0];
    const int *nrows, *ncols;
    if (n_in >= 5) {          // order: s, n1, n2, nrows, ncols
        nrows = (const int*)d_in[3];
        ncols = (const int*)d_in[4];
    } else {                  // fallback: s, nrows, ncols
        nrows = (const int*)d_in[1];
        ncols = (const int*)d_in[2];
    }
    float* out = (float*)d_out;

    const dim3 blk(256);
    const dim3 pgrid(NN / RPC, GRP);          // 32 row-CTAs x 32 batches

    float* acc = (float*)g_acc;               // device-symbol address is fine
    // (taking address of __device__ array in host code is invalid; use
    //  kernel-side indexing instead: pass pass-index derived pointers)
    (void)acc;

    zero_acc_kernel<<<(5 * NB * NN + 255) / 256, blk>>>();

    for (int g = 0; g < NB / GRP; g++) {
        const int b0 = g * GRP;
        // pass0: u=1 -> acc0
        pass_kernel<1><<<pgrid, blk>>>(s, nrows, ncols, nullptr, g_acc[0], b0);
        // passes 1..4: v=1/acc[k-1] -> acc[k]
        pass_kernel<0><<<pgrid, blk>>>(s, nrows, ncols, g_acc[0], g_acc[1], b0);
        pass_kernel<0><<<pgrid, blk>>>(s, nrows, ncols, g_acc[1], g_acc[2], b0);
        pass_kernel<0><<<pgrid, blk>>>(s, nrows, ncols, g_acc[2], g_acc[3], b0);
        pass_kernel<0><<<pgrid, blk>>>(s, nrows, ncols, g_acc[3], g_acc[4], b0);
        // final: v8=1/acc4, u9, write out
        final_kernel<<<pgrid, blk>>>(s, out, nrows, ncols, g_acc[4], b0);
    }
}

// round 14
// speedup vs baseline: 4.6297x; 4.6297x over previous
#include <cuda_runtime.h>

// Sinkhorn as diagonal scaling: out = (s+eps)*u9[r]*v8[c] on valid block.
// v_{2k} = 1/(M^T u_{2k-1}), u_{2k+1} = 1/(M v_{2k}), u0 = 1 on valid rows.
//
// R14 == R12 with the device-symbol bug fixed: R13 passed host-side addresses
// of __device__ g_acc to kernels; ATS made it *correct* but routed all
// accumulator traffic over NVLink-C2C host memory (313GB/s, 1222cyc) ->
// 1926us. Kernels now take a PASS INDEX and index g_acc in device code.
// Structure: 2 groups of 32 batches (L2 residency), finalize_v fused into
// each pass (v = 1/acc[kprev] computed inline), 13 launches total.

#define NB   64
#define NN   1024
#define EPS  1e-4f
#define GRP  32      // batches per group (L2 residency)
#define RPC  32      // rows per CTA

// Per-pass column-sum accumulators (allocation-free rule: __device__ globals).
// Buffer k is written by pass k and read (as v) by pass k+1 / final.
// Groups reuse buffers on disjoint batch ranges -> one upfront zero suffices.
__device__ float g_acc[5][NB * NN];

__global__ void zero_acc_kernel() {
    int i = blockIdx.x * blockDim.x + threadIdx.x;
    if (i < 5 * NB * NN) ((float*)g_acc)[i] = 0.0f;
}

// Build v for this batch from a finished accumulator buffer.
// v_c = (c < nc) ? 1/acc_c : 0, in registers (chunk f, lane-local cols).
__device__ __forceinline__ void build_v(float4 (&v4)[8], int kprev,
                                        int b, int nc, int mylim, int lane)
{
    const float4* ap = (const float4*)(&g_acc[kprev][b * NN]);
#pragma unroll
    for (int f = 0; f < 8; f++) {
        if (128 * f < mylim) {
            float4 a = ap[f * 32 + lane];
            const int c0 = 128 * f + 4 * lane;
            v4[f].x = (c0 + 0 < nc) ? (1.0f / a.x) : 0.0f;
            v4[f].y = (c0 + 1 < nc) ? (1.0f / a.y) : 0.0f;
            v4[f].z = (c0 + 2 < nc) ? (1.0f / a.z) : 0.0f;
            v4[f].w = (c0 + 3 < nc) ? (1.0f / a.w) : 0.0f;
        } else {
            v4[f] = make_float4(0.f, 0.f, 0.f, 0.f);
        }
    }
}

// One streaming pass. FIRST=1: u=1 (computes c0 into g_acc[0]).
// FIRST=0: v = 1/g_acc[knext-1]; per valid row: u = 1/dot(row+eps, v);
//          g_acc[knext][c] += (row[c]+eps)*u.
template <int FIRST>
__global__ __launch_bounds__(256, 2) void pass_kernel(
    const float* __restrict__ s,
    const int*   __restrict__ nrows,
    const int*   __restrict__ ncols,
    int knext,
    int batch0)
{
    const int b  = batch0 + blockIdx.y;
    const int nr = nrows[b];
    const int r0cta = blockIdx.x * RPC;
    if (r0cta >= nr) return;   // whole CTA invalid (uniform exit, no syncs yet)

    const int nc   = ncols[b];
    const int warp = threadIdx.x >> 5;
    const int lane = threadIdx.x & 31;
    const int mylim = nc - 4 * lane;   // chunk f needed iff 128*f < mylim

    const float4* sb = (const float4*)(s + (size_t)b * NN * NN);

    float4 v4[8];
    if (FIRST) {
#pragma unroll
        for (int f = 0; f < 8; f++) v4[f] = make_float4(0.f, 0.f, 0.f, 0.f);
    } else {
        build_v(v4, knext - 1, b, nc, mylim, lane);
    }

    float4 acc[8];
#pragma unroll
    for (int f = 0; f < 8; f++) acc[f] = make_float4(0.f, 0.f, 0.f, 0.f);

    const int rbase = r0cta + warp * 4;
    for (int i = 0; i < 4; i++) {
        int r = rbase + i;
        if (r >= nr) break;          // warp-uniform
        const float4* rp = sb + (size_t)r * 256;

        float4 x[8];
#pragma unroll
        for (int f = 0; f < 8; f++)
            if (128 * f < mylim) x[f] = rp[f * 32 + lane];
#pragma unroll
        for (int f = 0; f < 8; f++)
            if (128 * f < mylim) { x[f].x += EPS; x[f].y += EPS; x[f].z += EPS; x[f].w += EPS; }

        float u;
        if (FIRST) {
            u = 1.0f;
        } else {
            float d = 0.0f;
#pragma unroll
            for (int f = 0; f < 8; f++)
                if (128 * f < mylim)
                    d += x[f].x * v4[f].x + x[f].y * v4[f].y
                       + x[f].z * v4[f].z + x[f].w * v4[f].w;
#pragma unroll
            for (int o = 16; o; o >>= 1) d += __shfl_xor_sync(0xffffffffu, d, o);
            u = 1.0f / d;
        }
#pragma unroll
        for (int f = 0; f < 8; f++)
            if (128 * f < mylim) {
                acc[f].x += x[f].x * u; acc[f].y += x[f].y * u;
                acc[f].z += x[f].z * u; acc[f].w += x[f].w * u;
            }
    }

    // CTA-level reduction of per-warp column accumulators, then REDG per col.
    __shared__ float4 st[8][256];
#pragma unroll
    for (int f = 0; f < 8; f++) st[warp][f * 32 + lane] = acc[f];
    __syncthreads();

    const int j = threadIdx.x;           // owns columns 4j..4j+3
    float4 t = st[0][j];
#pragma unroll
    for (int w = 1; w < 8; w++) {
        float4 a = st[w][j];
        t.x += a.x; t.y += a.y; t.z += a.z; t.w += a.w;
    }
    float* ga = &g_acc[knext][b * NN + 4 * j];
    atomicAdd(ga + 0, t.x);
    atomicAdd(ga + 1, t.y);
    atomicAdd(ga + 2, t.z);
    atomicAdd(ga + 3, t.w);
}

// Final pass: v8 = 1/g_acc[4]; u9 = 1/(M v8); out = (s+eps)*u9*v8 (0 outside).
__global__ __launch_bounds__(256, 2) void final_kernel(
    const float* __restrict__ s,
    float*       __restrict__ out,
    const int*   __restrict__ nrows,
    const int*   __restrict__ ncols,
    int batch0)
{
    const int b  = batch0 + blockIdx.y;
    const int nr = nrows[b];
    const int nc = ncols[b];
    const int warp = threadIdx.x >> 5;
    const int lane = threadIdx.x & 31;
    const int mylim = nc - 4 * lane;

    const float4* sb = (const float4*)(s + (size_t)b * NN * NN);
    float4*       ob = (float4*)(out + (size_t)b * NN * NN);

    float4 v4[8];
    build_v(v4, 4, b, nc, mylim, lane);

    const int rbase = blockIdx.x * RPC + warp * 4;
    const float4 z4 = make_float4(0.f, 0.f, 0.f, 0.f);

    for (int i = 0; i < 4; i++) {
        int r = rbase + i;
        float4* op = ob + (size_t)r * 256;
        if (r >= nr) {                     // invalid row: all zeros (no read)
#pragma unroll
            for (int f = 0; f < 8; f++) __stcs(&op[f * 32 + lane], z4);
            continue;
        }
        const float4* rp = sb + (size_t)r * 256;
        float4 x[8];
#pragma unroll
        for (int f = 0; f < 8; f++)
            if (128 * f < mylim) x[f] = rp[f * 32 + lane];
#pragma unroll
        for (int f = 0; f < 8; f++)
            if (128 * f < mylim) { x[f].x += EPS; x[f].y += EPS; x[f].z += EPS; x[f].w += EPS; }

        float d = 0.0f;
#pragma unroll
        for (int f = 0; f < 8; f++)
            if (128 * f < mylim)
                d += x[f].x * v4[f].x + x[f].y * v4[f].y
                   + x[f].z * v4[f].z + x[f].w * v4[f].w;
#pragma unroll
        for (int o = 16; o; o >>= 1) d += __shfl_xor_sync(0xffffffffu, d, o);
        const float u = 1.0f / d;

#pragma unroll
        for (int f = 0; f < 8; f++) {
            if (128 * f < mylim) {
                float4 o;
                o.x = x[f].x * u * v4[f].x;
                o.y = x[f].y * u * v4[f].y;
                o.z = x[f].z * u * v4[f].z;
                o.w = x[f].w * u * v4[f].w;
                __stcs(&op[f * 32 + lane], o);   // v==0 beyond ncols -> exact 0
            } else {
                __stcs(&op[f * 32 + lane], z4);
            }
        }
    }
}

extern "C" void kernel_launch(void* const* d_in, const int* in_sizes, int n_in,
                              void* d_out, int out_size)
{
    const float* s = (const float*)d_in[0];
    const int *nrows, *ncols;
    if (n_in >= 5) {          // order: s, n1, n2, nrows, ncols
        nrows = (const int*)d_in[3];
        ncols = (const int*)d_in[4];
    } else {                  // fallback: s, nrows, ncols
        nrows = (const int*)d_in[1];
        ncols = (const int*)d_in[2];
    }
    float* out = (float*)d_out;

    const dim3 blk(256);
    const dim3 pgrid(NN / RPC, GRP);          // 32 row-CTAs x 32 batches

    zero_acc_kernel<<<(5 * NB * NN + 255) / 256, blk>>>();

    for (int g = 0; g < NB / GRP; g++) {
        const int b0 = g * GRP;
        pass_kernel<1><<<pgrid, blk>>>(s, nrows, ncols, 0, b0);  // u=1 -> acc0
        pass_kernel<0><<<pgrid, blk>>>(s, nrows, ncols, 1, b0);  // v0 -> acc1
        pass_kernel<0><<<pgrid, blk>>>(s, nrows, ncols, 2, b0);  // v2 -> acc2
        pass_kernel<0><<<pgrid, blk>>>(s, nrows, ncols, 3, b0);  // v4 -> acc3
        pass_kernel<0><<<pgrid, blk>>>(s, nrows, ncols, 4, b0);  // v6 -> acc4
        final_kernel<<<pgrid, blk>>>(s, out, nrows, ncols, b0);  // v8, u9 -> out
    }
}

// round 15
// speedup vs baseline: 8.4730x; 1.8301x over previous
#include <cuda_runtime.h>
#include <cuda_fp16.h>

// Sinkhorn as diagonal scaling: out = (s+eps)*u9[r]*v8[c] on valid block.
// v_{2k} = 1/(M^T u_{2k-1}), u_{2k+1} = 1/(M v_{2k}), u0 = 1 on valid rows.
//
// R15 = R2 champion kernels (verbatim bodies, separate finalize kernels that
// proved fast) + ONE change: pass 0 caches fp16(s+eps) in a 128MB device
// scratch; passes 1-4 read fp16 (valid footprint ~81MB -> fully L2-resident
// across ALL 64 batches, no group split). Final pass re-reads fp32 s so the
// output error stays ~1e-4 (gate: 1e-3). 12 launches.

#define NB   1 * 64
#define NN   1024
#define EPS  1e-4f
#define RPC  32      // rows per CTA

__device__ __half g_s16[(size_t)NB * NN * NN];  // fp16(s+eps), valid region only
__device__ float  g_acc[NB * NN];               // column-sum accumulator
__device__ float  g_v[NB * NN];                 // current column scales

__global__ void zero_acc_kernel() {
    int i = blockIdx.x * blockDim.x + threadIdx.x;
    if (i < NB * NN) g_acc[i] = 0.0f;
}

__global__ void finalize_v_kernel(const int* __restrict__ ncols) {
    int i = blockIdx.x * blockDim.x + threadIdx.x;
    if (i >= NB * NN) return;
    int b = i >> 10;
    int c = i & 1023;
    float a = g_acc[i];
    g_v[i]   = (c < ncols[b]) ? (1.0f / a) : 0.0f;
    g_acc[i] = 0.0f;   // ready for the next accumulating pass
}

// Pass 0: u=1. Reads fp32 s, accumulates column sums (fp32), and caches
// fp16(s+eps) into g_s16 for the middle passes (plain stores: keep in L2).
__global__ __launch_bounds__(256, 2) void pass0_kernel(
    const float* __restrict__ s,
    const int*   __restrict__ nrows,
    const int*   __restrict__ ncols)
{
    const int b  = blockIdx.y;
    const int nr = nrows[b];
    const int r0cta = blockIdx.x * RPC;
    if (r0cta >= nr) return;   // uniform exit before any sync

    const int nc   = ncols[b];
    const int warp = threadIdx.x >> 5;
    const int lane = threadIdx.x & 31;
    const int mylim = nc - 4 * lane;   // chunk f needed iff 128*f < mylim

    const float4* sb   = (const float4*)(s + (size_t)b * NN * NN);
    uint2*        sb16 = (uint2*)(g_s16 + (size_t)b * NN * NN);

    float4 acc[8];
#pragma unroll
    for (int f = 0; f < 8; f++) acc[f] = make_float4(0.f, 0.f, 0.f, 0.f);

    const int rbase = r0cta + warp * 4;
    for (int i = 0; i < 4; i++) {
        int r = rbase + i;
        if (r >= nr) break;          // warp-uniform
        const float4* rp = sb   + (size_t)r * 256;
        uint2*        wp = sb16 + (size_t)r * 256;

        float4 x[8];
#pragma unroll
        for (int f = 0; f < 8; f++)
            if (128 * f < mylim) x[f] = rp[f * 32 + lane];
#pragma unroll
        for (int f = 0; f < 8; f++)
            if (128 * f < mylim) { x[f].x += EPS; x[f].y += EPS; x[f].z += EPS; x[f].w += EPS; }

#pragma unroll
        for (int f = 0; f < 8; f++)
            if (128 * f < mylim) {
                acc[f].x += x[f].x; acc[f].y += x[f].y;
                acc[f].z += x[f].z; acc[f].w += x[f].w;
                __half2 h0 = __floats2half2_rn(x[f].x, x[f].y);
                __half2 h1 = __floats2half2_rn(x[f].z, x[f].w);
                uint2 pk;
                pk.x = *reinterpret_cast<const unsigned int*>(&h0);
                pk.y = *reinterpret_cast<const unsigned int*>(&h1);
                wp[f * 32 + lane] = pk;   // default store: L2-resident
            }
    }

    __shared__ float4 st[8][256];
#pragma unroll
    for (int f = 0; f < 8; f++) st[warp][f * 32 + lane] = acc[f];
    __syncthreads();

    const int j = threadIdx.x;           // owns columns 4j..4j+3
    float4 t = st[0][j];
#pragma unroll
    for (int w = 1; w < 8; w++) {
        float4 a = st[w][j];
        t.x += a.x; t.y += a.y; t.z += a.z; t.w += a.w;
    }
    float* ga = g_acc + b * NN + 4 * j;
    atomicAdd(ga + 0, t.x);
    atomicAdd(ga + 1, t.y);
    atomicAdd(ga + 2, t.z);
    atomicAdd(ga + 3, t.w);
}

// Middle passes 1..4: read fp16(s+eps) (eps baked in) + g_v.
// Per valid row: u = 1/dot(row16, v); g_acc[c] += row16[c]*u.
__global__ __launch_bounds__(256, 2) void pass16_kernel(
    const int* __restrict__ nrows,
    const int* __restrict__ ncols)
{
    const int b  = blockIdx.y;
    const int nr = nrows[b];
    const int r0cta = blockIdx.x * RPC;
    if (r0cta >= nr) return;

    const int nc   = ncols[b];
    const int warp = threadIdx.x >> 5;
    const int lane = threadIdx.x & 31;
    const int mylim = nc - 4 * lane;

    const uint2* sb16 = (const uint2*)(g_s16 + (size_t)b * NN * NN);

    float4 v4[8];
    {
        const float4* vb = (const float4*)(g_v + b * NN);
#pragma unroll
        for (int f = 0; f < 8; f++)
            v4[f] = (128 * f < mylim) ? vb[f * 32 + lane]
                                      : make_float4(0.f, 0.f, 0.f, 0.f);
    }

    float4 acc[8];
#pragma unroll
    for (int f = 0; f < 8; f++) acc[f] = make_float4(0.f, 0.f, 0.f, 0.f);

    const int rbase = r0cta + warp * 4;
    for (int i = 0; i < 4; i++) {
        int r = rbase + i;
        if (r >= nr) break;          // warp-uniform
        const uint2* rp = sb16 + (size_t)r * 256;

        float4 x[8];
#pragma unroll
        for (int f = 0; f < 8; f++)
            if (128 * f < mylim) {
                uint2 raw = rp[f * 32 + lane];
                float2 f01 = __half22float2(*reinterpret_cast<const __half2*>(&raw.x));
                float2 f23 = __half22float2(*reinterpret_cast<const __half2*>(&raw.y));
                x[f] = make_float4(f01.x, f01.y, f23.x, f23.y);
            }

        float d = 0.0f;
#pragma unroll
        for (int f = 0; f < 8; f++)
            if (128 * f < mylim)
                d += x[f].x * v4[f].x + x[f].y * v4[f].y
                   + x[f].z * v4[f].z + x[f].w * v4[f].w;
#pragma unroll
        for (int o = 16; o; o >>= 1) d += __shfl_xor_sync(0xffffffffu, d, o);
        const float u = 1.0f / d;

#pragma unroll
        for (int f = 0; f < 8; f++)
            if (128 * f < mylim) {
                acc[f].x += x[f].x * u; acc[f].y += x[f].y * u;
                acc[f].z += x[f].z * u; acc[f].w += x[f].w * u;
            }
    }

    __shared__ float4 st[8][256];
#pragma unroll
    for (int f = 0; f < 8; f++) st[warp][f * 32 + lane] = acc[f];
    __syncthreads();

    const int j = threadIdx.x;
    float4 t = st[0][j];
#pragma unroll
    for (int w = 1; w < 8; w++) {
        float4 a = st[w][j];
        t.x += a.x; t.y += a.y; t.z += a.z; t.w += a.w;
    }
    float* ga = g_acc + b * NN + 4 * j;
    atomicAdd(ga + 0, t.x);
    atomicAdd(ga + 1, t.y);
    atomicAdd(ga + 2, t.z);
    atomicAdd(ga + 3, t.w);
}

// Final pass: v8 = g_v; u9 = 1/dot(row_fp32+eps, v8); out = (s+eps)*u9*v8.
__global__ __launch_bounds__(256, 2) void final_kernel(
    const float* __restrict__ s,
    float*       __restrict__ out,
    const int*   __restrict__ nrows,
    const int*   __restrict__ ncols)
{
    const int b  = blockIdx.y;
    const int nr = nrows[b];
    const int nc = ncols[b];
    const int warp = threadIdx.x >> 5;
    const int lane = threadIdx.x & 31;
    const int mylim = nc - 4 * lane;

    const float4* sb = (const float4*)(s + (size_t)b * NN * NN);
    float4*       ob = (float4*)(out + (size_t)b * NN * NN);
    const float4* vb = (const float4*)(g_v + b * NN);

    float4 v4[8];
#pragma unroll
    for (int f = 0; f < 8; f++)
        v4[f] = (128 * f < mylim) ? vb[f * 32 + lane]
                                  : make_float4(0.f, 0.f, 0.f, 0.f);

    const int rbase = blockIdx.x * RPC + warp * 4;
    const float4 z4 = make_float4(0.f, 0.f, 0.f, 0.f);

    for (int i = 0; i < 4; i++) {
        int r = rbase + i;
        float4* op = ob + (size_t)r * 256;
        if (r >= nr) {                     // invalid row: all zeros (no read)
#pragma unroll
            for (int f = 0; f < 8; f++) __stcs(&op[f * 32 + lane], z4);
            continue;
        }
        const float4* rp = sb + (size_t)r * 256;
        float4 x[8];
#pragma unroll
        for (int f = 0; f < 8; f++)
            if (128 * f < mylim) x[f] = rp[f * 32 + lane];
#pragma unroll
        for (int f = 0; f < 8; f++)
            if (128 * f < mylim) { x[f].x += EPS; x[f].y += EPS; x[f].z += EPS; x[f].w += EPS; }

        float d = 0.0f;
#pragma unroll
        for (int f = 0; f < 8; f++)
            if (128 * f < mylim)
                d += x[f].x * v4[f].x + x[f].y * v4[f].y
                   + x[f].z * v4[f].z + x[f].w * v4[f].w;
#pragma unroll
        for (int o = 16; o; o >>= 1) d += __shfl_xor_sync(0xffffffffu, d, o);
        const float u = 1.0f / d;

#pragma unroll
        for (int f = 0; f < 8; f++) {
            if (128 * f < mylim) {
                float4 o;
                o.x = x[f].x * u * v4[f].x;
                o.y = x[f].y * u * v4[f].y;
                o.z = x[f].z * u * v4[f].z;
                o.w = x[f].w * u * v4[f].w;
                __stcs(&op[f * 32 + lane], o);   // v==0 beyond ncols -> exact 0
            } else {
                __stcs(&op[f * 32 + lane], z4);
            }
        }
    }
}

extern "C" void kernel_launch(void* const* d_in, const int* in_sizes, int n_in,
                              void* d_out, int out_size)
{
    const float* s = (const float*)d_in[0];
    const int *nrows, *ncols;
    if (n_in >= 5) {          // order: s, n1, n2, nrows, ncols
        nrows = (const int*)d_in[3];
        ncols = (const int*)d_in[4];
    } else {                  // fallback: s, nrows, ncols
        nrows = (const int*)d_in[1];
        ncols = (const int*)d_in[2];
    }
    float* out = (float*)d_out;

    const dim3 blk(256);
    const dim3 pgrid(NN / RPC, NB);           // 32 row-CTAs x ALL 64 batches
    const dim3 fgrid((NB * NN) / 256);

    zero_acc_kernel<<<fgrid, blk>>>();
    pass0_kernel<<<pgrid, blk>>>(s, nrows, ncols);    // c0 + s16 cache
    finalize_v_kernel<<<fgrid, blk>>>(ncols);         // v0
    for (int k = 0; k < 4; k++) {
        pass16_kernel<<<pgrid, blk>>>(nrows, ncols);  // (r,c) pairs on fp16
        finalize_v_kernel<<<fgrid, blk>>>(ncols);     // v2, v4, v6, v8
    }
    final_kernel<<<pgrid, blk>>>(s, out, nrows, ncols);  // u9 -> output (fp32)
}

// round 17
// speedup vs baseline: 8.7640x; 1.0344x over previous
#include <cuda_runtime.h>
#include <cuda_fp16.h>

// Sinkhorn as diagonal scaling: out = (s+eps)*u9[r]*v8[c] on valid block.
// v_{2k} = 1/(M^T u_{2k-1}), u_{2k+1} = 1/(M v_{2k}), u0 = 1 on valid rows.
//
// R16 = R15 champion (fp16 cache of s+eps for middle passes, all 64 batches
// L2-resident) with pass16 rebuilt for latency tolerance: warp = HALF-row
// (512 cols, 4 fp16 chunks) so the kernel fits 64 regs -> 4 CTAs/SM
// (32 warps, 2x), dots combined across halves via d_s[2][32] + one sync.
// pass0 / finalize / final are untouched R15 bodies.

#define NB   64
#define NN   1024
#define EPS  1e-4f
#define RPC  32      // rows per CTA

__device__ __half g_s16[(size_t)NB * NN * NN];  // fp16(s+eps), valid region only
__device__ float  g_acc[NB * NN];               // column-sum accumulator
__device__ float  g_v[NB * NN];                 // current column scales

__global__ void zero_acc_kernel() {
    int i = blockIdx.x * blockDim.x + threadIdx.x;
    if (i < NB * NN) g_acc[i] = 0.0f;
}

__global__ void finalize_v_kernel(const int* __restrict__ ncols) {
    int i = blockIdx.x * blockDim.x + threadIdx.x;
    if (i >= NB * NN) return;
    int b = i >> 10;
    int c = i & 1023;
    float a = g_acc[i];
    g_v[i]   = (c < ncols[b]) ? (1.0f / a) : 0.0f;
    g_acc[i] = 0.0f;   // ready for the next accumulating pass
}

// Pass 0: u=1. Reads fp32 s, accumulates column sums, caches fp16(s+eps).
__global__ __launch_bounds__(256, 2) void pass0_kernel(
    const float* __restrict__ s,
    const int*   __restrict__ nrows,
    const int*   __restrict__ ncols)
{
    const int b  = blockIdx.y;
    const int nr = nrows[b];
    const int r0cta = blockIdx.x * RPC;
    if (r0cta >= nr) return;   // uniform exit before any sync

    const int nc   = ncols[b];
    const int warp = threadIdx.x >> 5;
    const int lane = threadIdx.x & 31;
    const int mylim = nc - 4 * lane;   // chunk f needed iff 128*f < mylim

    const float4* sb   = (const float4*)(s + (size_t)b * NN * NN);
    uint2*        sb16 = (uint2*)(g_s16 + (size_t)b * NN * NN);

    float4 acc[8];
#pragma unroll
    for (int f = 0; f < 8; f++) acc[f] = make_float4(0.f, 0.f, 0.f, 0.f);

    const int rbase = r0cta + warp * 4;
    for (int i = 0; i < 4; i++) {
        int r = rbase + i;
        if (r >= nr) break;          // warp-uniform
        const float4* rp = sb   + (size_t)r * 256;
        uint2*        wp = sb16 + (size_t)r * 256;

        float4 x[8];
#pragma unroll
        for (int f = 0; f < 8; f++)
            if (128 * f < mylim) x[f] = rp[f * 32 + lane];
#pragma unroll
        for (int f = 0; f < 8; f++)
            if (128 * f < mylim) { x[f].x += EPS; x[f].y += EPS; x[f].z += EPS; x[f].w += EPS; }

#pragma unroll
        for (int f = 0; f < 8; f++)
            if (128 * f < mylim) {
                acc[f].x += x[f].x; acc[f].y += x[f].y;
                acc[f].z += x[f].z; acc[f].w += x[f].w;
                __half2 h0 = __floats2half2_rn(x[f].x, x[f].y);
                __half2 h1 = __floats2half2_rn(x[f].z, x[f].w);
                uint2 pk;
                pk.x = *reinterpret_cast<const unsigned int*>(&h0);
                pk.y = *reinterpret_cast<const unsigned int*>(&h1);
                wp[f * 32 + lane] = pk;   // default store: L2-resident
            }
    }

    __shared__ float4 st[8][256];
#pragma unroll
    for (int f = 0; f < 8; f++) st[warp][f * 32 + lane] = acc[f];
    __syncthreads();

    const int j = threadIdx.x;           // owns columns 4j..4j+3
    float4 t = st[0][j];
#pragma unroll
    for (int w = 1; w < 8; w++) {
        float4 a = st[w][j];
        t.x += a.x; t.y += a.y; t.z += a.z; t.w += a.w;
    }
    float* ga = g_acc + b * NN + 4 * j;
    atomicAdd(ga + 0, t.x);
    atomicAdd(ga + 1, t.y);
    atomicAdd(ga + 2, t.z);
    atomicAdd(ga + 3, t.w);
}

// Middle passes 1..4, rebuilt: warp = half-row (4 fp16 chunks), 64 regs,
// 4 CTAs/SM. Phase1: half-row dots -> d_s; sync; phase2: re-stream rows
// (L1/L2 hot) accumulating columns with u = 1/(d0+d1).
__global__ __launch_bounds__(256, 4) void pass16_kernel(
    const int* __restrict__ nrows,
    const int* __restrict__ ncols)
{
    __shared__ float  d_s[2][RPC];
    __shared__ float4 stage[8][128];

    const int b  = blockIdx.y;
    const int nr = nrows[b];
    const int r0cta = blockIdx.x * RPC;
    if (r0cta >= nr) return;             // uniform CTA exit before syncs

    const int nc   = ncols[b];
    const int warp = threadIdx.x >> 5;
    const int lane = threadIdx.x & 31;
    const int half = warp >> 2;          // column half 0/1
    const int wseq = warp & 3;           // row-group within half
    // chunk f covers cols half*512 + 128f + 4lane..+3; needed iff 128f < mylim
    const int mylim = nc - half * 512 - 4 * lane;

    const uint2* sb16 = (const uint2*)(g_s16 + (size_t)b * NN * NN);

    float4 v4[4];
    {
        const float4* vb = (const float4*)(g_v + b * NN);
#pragma unroll
        for (int f = 0; f < 4; f++)
            v4[f] = (128 * f < mylim) ? vb[(half * 4 + f) * 32 + lane]
                                      : make_float4(0.f, 0.f, 0.f, 0.f);
    }

    const int rbase = r0cta + wseq * 8;        // first global row of warp
    const int lbase = wseq * 8;                // first CTA-local row
    const int cnt   = max(0, min(8, nr - rbase));

    // ---- phase 1: half-row dots in 2 groups of 4 (pipelined chains)
    for (int g = 0; g < 2; g++) {
        const int i0 = g * 4;
        const int gc = cnt - i0;
        if (gc <= 0) break;                    // warp-uniform
        float4 dv[4];
#pragma unroll
        for (int i = 0; i < 4; i++) dv[i] = make_float4(0.f, 0.f, 0.f, 0.f);
#pragma unroll
        for (int i = 0; i < 4; i++) {
            if (i >= gc) break;
            const uint2* rp = sb16 + (size_t)(rbase + i0 + i) * 256;
#pragma unroll
            for (int f = 0; f < 4; f++)
                if (128 * f < mylim) {
                    uint2 raw = rp[(half * 4 + f) * 32 + lane];
                    float2 f01 = __half22float2(*reinterpret_cast<const __half2*>(&raw.x));
                    float2 f23 = __half22float2(*reinterpret_cast<const __half2*>(&raw.y));
                    dv[i].x += f01.x * v4[f].x;
                    dv[i].y += f01.y * v4[f].y;
                    dv[i].z += f23.x * v4[f].z;
                    dv[i].w += f23.y * v4[f].w;
                }
        }
        float d[4];
#pragma unroll
        for (int i = 0; i < 4; i++)
            d[i] = (dv[i].x + dv[i].y) + (dv[i].z + dv[i].w);
#pragma unroll
        for (int o = 16; o; o >>= 1) {
#pragma unroll
            for (int i = 0; i < 4; i++)
                d[i] += __shfl_xor_sync(0xffffffffu, d[i], o);
        }
        if (lane == 0) {
            d_s[half][lbase + i0] = d[0];
            if (gc > 1) d_s[half][lbase + i0 + 1] = d[1];
            if (gc > 2) d_s[half][lbase + i0 + 2] = d[2];
            if (gc > 3) d_s[half][lbase + i0 + 3] = d[3];
        }
    }
    __syncthreads();

    // ---- phase 2: re-stream rows, accumulate columns with u = 1/(d0+d1)
    float4 acc[4];
#pragma unroll
    for (int f = 0; f < 4; f++) acc[f] = make_float4(0.f, 0.f, 0.f, 0.f);

    for (int i = 0; i < 8; i++) {
        if (i >= cnt) break;                   // warp-uniform
        const float u = 1.0f / (d_s[0][lbase + i] + d_s[1][lbase + i]);
        const uint2* rp = sb16 + (size_t)(rbase + i) * 256;
#pragma unroll
        for (int f = 0; f < 4; f++)
            if (128 * f < mylim) {
                uint2 raw = rp[(half * 4 + f) * 32 + lane];
                float2 f01 = __half22float2(*reinterpret_cast<const __half2*>(&raw.x));
                float2 f23 = __half22float2(*reinterpret_cast<const __half2*>(&raw.y));
                acc[f].x += f01.x * u;
                acc[f].y += f01.y * u;
                acc[f].z += f23.x * u;
                acc[f].w += f23.y * u;
            }
    }

    // ---- CTA column reduction (4 warps per half), then REDG per column
#pragma unroll
    for (int f = 0; f < 4; f++) stage[warp][f * 32 + lane] = acc[f];
    __syncthreads();
    {
        const int h = threadIdx.x >> 7;        // column half
        const int j = threadIdx.x & 127;       // float4 slot within half
        float4 t = stage[h * 4][j];
#pragma unroll
        for (int k = 1; k < 4; k++) {
            float4 a = stage[h * 4 + k][j];
            t.x += a.x; t.y += a.y; t.z += a.z; t.w += a.w;
        }
        float* ga = g_acc + b * NN + h * 512 + (j >> 5) * 128 + 4 * (j & 31);
        atomicAdd(ga + 0, t.x);
        atomicAdd(ga + 1, t.y);
        atomicAdd(ga + 2, t.z);
        atomicAdd(ga + 3, t.w);
    }
}

// Final pass: v8 = g_v; u9 = 1/dot(row_fp32+eps, v8); out = (s+eps)*u9*v8.
__global__ __launch_bounds__(256, 2) void final_kernel(
    const float* __restrict__ s,
    float*       __restrict__ out,
    const int*   __restrict__ nrows,
    const int*   __restrict__ ncols)
{
    const int b  = blockIdx.y;
    const int nr = nrows[b];
    const int nc = ncols[b];
    const int warp = threadIdx.x >> 5;
    const int lane = threadIdx.x & 31;
    const int mylim = nc - 4 * lane;

    const float4* sb = (const float4*)(s + (size_t)b * NN * NN);
    float4*       ob = (float4*)(out + (size_t)b * NN * NN);
    const float4* vb = (const float4*)(g_v + b * NN);

    float4 v4[8];
#pragma unroll
    for (int f = 0; f < 8; f++)
        v4[f] = (128 * f < mylim) ? vb[f * 32 + lane]
                                  : make_float4(0.f, 0.f, 0.f, 0.f);

    const int rbase = blockIdx.x * RPC + warp * 4;
    const float4 z4 = make_float4(0.f, 0.f, 0.f, 0.f);

    for (int i = 0; i < 4; i++) {
        int r = rbase + i;
        float4* op = ob + (size_t)r * 256;
        if (r >= nr) {                     // invalid row: all zeros (no read)
#pragma unroll
            for (int f = 0; f < 8; f++) __stcs(&op[f * 32 + lane], z4);
            continue;
        }
        const float4* rp = sb + (size_t)r * 256;
        float4 x[8];
#pragma unroll
        for (int f = 0; f < 8; f++)
            if (128 * f < mylim) x[f] = rp[f * 32 + lane];
#pragma unroll
        for (int f = 0; f < 8; f++)
            if (128 * f < mylim) { x[f].x += EPS; x[f].y += EPS; x[f].z += EPS; x[f].w += EPS; }

        float d = 0.0f;
#pragma unroll
        for (int f = 0; f < 8; f++)
            if (128 * f < mylim)
                d += x[f].x * v4[f].x + x[f].y * v4[f].y
                   + x[f].z * v4[f].z + x[f].w * v4[f].w;
#pragma unroll
        for (int o = 16; o; o >>= 1) d += __shfl_xor_sync(0xffffffffu, d, o);
        const float u = 1.0f / d;

#pragma unroll
        for (int f = 0; f < 8; f++) {
            if (128 * f < mylim) {
                float4 o;
                o.x = x[f].x * u * v4[f].x;
                o.y = x[f].y * u * v4[f].y;
                o.z = x[f].z * u * v4[f].z;
                o.w = x[f].w * u * v4[f].w;
                __stcs(&op[f * 32 + lane], o);   // v==0 beyond ncols -> exact 0
            } else {
                __stcs(&op[f * 32 + lane], z4);
            }
        }
    }
}

extern "C" void kernel_launch(void* const* d_in, const int* in_sizes, int n_in,
                              void* d_out, int out_size)
{
    const float* s = (const float*)d_in[0];
    const int *nrows, *ncols;
    if (n_in >= 5) {          // order: s, n1, n2, nrows, ncols
        nrows = (const int*)d_in[3];
        ncols = (const int*)d_in[4];
    } else {                  // fallback: s, nrows, ncols
        nrows = (const int*)d_in[1];
        ncols = (const int*)d_in[2];
    }
    float* out = (float*)d_out;

    const dim3 blk(256);
    const dim3 pgrid(NN / RPC, NB);           // 32 row-CTAs x ALL 64 batches
    const dim3 fgrid((NB * NN) / 256);

    zero_acc_kernel<<<fgrid, blk>>>();
    pass0_kernel<<<pgrid, blk>>>(s, nrows, ncols);    // c0 + s16 cache
    finalize_v_kernel<<<fgrid, blk>>>(ncols);         // v0
    for (int k = 0; k < 4; k++) {
        pass16_kernel<<<pgrid, blk>>>(nrows, ncols);  // (r,c) pairs on fp16
        finalize_v_kernel<<<fgrid, blk>>>(ncols);     // v2, v4, v6, v8
    }
    final_kernel<<<pgrid, blk>>>(s, out, nrows, ncols);  // u9 -> output (fp32)
}